// round 12
// baseline (speedup 1.0000x reference)
#include <cuda_runtime.h>
#include <cuda_bf16.h>
#include <math.h>

#define B_  16
#define N_  1024
#define C_  768
#define H_  12
#define HD_ 64
#define NC3 2304
#define MROWS (B_*N_)
#define KP  (C_/2)          // 384 k-pairs
#define BHROWS (B_*H_*N_)   // 196608

// f32 scratch
__device__ float g_q[B_*H_*N_*HD_];
__device__ float g_k[B_*H_*N_*HD_];
__device__ float g_v[B_*H_*N_*HD_];
// packed bf16x2 (pairs along k) scratch
__device__ unsigned g_xh[MROWS*KP],  g_xl[MROWS*KP];
__device__ unsigned g_wqh[KP*NC3],   g_wql[KP*NC3];
__device__ unsigned g_wph[KP*C_],    g_wpl[KP*C_];
__device__ unsigned g_oh[MROWS*KP],  g_ol[MROWS*KP];
__device__ unsigned g_kph[BHROWS*32], g_kpl[BHROWS*32];       // [bh*N+key][dpair]
__device__ unsigned g_vph[B_*H_*64*512], g_vpl[B_*H_*64*512]; // [bh*64+d][keypair]

// ---------------------------------------------------------------------------
// helpers
// ---------------------------------------------------------------------------
__device__ __forceinline__ void bsplit2(float x, float y, unsigned& h, unsigned& l) {
    unsigned hb;
    asm("cvt.rn.bf16x2.f32 %0, %1, %2;" : "=r"(hb) : "f"(y), "f"(x));
    float hx = __uint_as_float(hb << 16);
    float hy = __uint_as_float(hb & 0xffff0000u);
    unsigned lb;
    asm("cvt.rn.bf16x2.f32 %0, %1, %2;" : "=r"(lb) : "f"(y - hy), "f"(x - hx));
    h = hb; l = lb;
}

__device__ __forceinline__ void mma_bf16(float d[4], const unsigned a[4], const unsigned b[2]) {
    asm volatile(
        "mma.sync.aligned.m16n8k16.row.col.f32.bf16.bf16.f32 "
        "{%0,%1,%2,%3}, {%4,%5,%6,%7}, {%8,%9}, {%0,%1,%2,%3};"
        : "+f"(d[0]), "+f"(d[1]), "+f"(d[2]), "+f"(d[3])
        : "r"(a[0]), "r"(a[1]), "r"(a[2]), "r"(a[3]), "r"(b[0]), "r"(b[1]));
}

__device__ __forceinline__ void cp_async16(void* sptr, const void* gptr) {
    unsigned s = (unsigned)__cvta_generic_to_shared(sptr);
    asm volatile("cp.async.cg.shared.global [%0], [%1], 16;" :: "r"(s), "l"(gptr));
}
#define CP_COMMIT() asm volatile("cp.async.commit_group;" ::: "memory")
#define CP_WAIT0()  asm volatile("cp.async.wait_group 0;" ::: "memory")

// ---------------------------------------------------------------------------
// Prep: split x into packed hi/lo (pairs along k).
// ---------------------------------------------------------------------------
__global__ __launch_bounds__(256) void split_x(const float* __restrict__ X) {
    int idx = blockIdx.x * 256 + threadIdx.x;     // [0, MROWS*48)
    int row = idx / 48, g = idx - row * 48;
    const float4* p = (const float4*)(X + (size_t)row * C_ + g * 16);
    float4 v0 = p[0], v1 = p[1], v2 = p[2], v3 = p[3];
    unsigned h[8], l[8];
    bsplit2(v0.x, v0.y, h[0], l[0]); bsplit2(v0.z, v0.w, h[1], l[1]);
    bsplit2(v1.x, v1.y, h[2], l[2]); bsplit2(v1.z, v1.w, h[3], l[3]);
    bsplit2(v2.x, v2.y, h[4], l[4]); bsplit2(v2.z, v2.w, h[5], l[5]);
    bsplit2(v3.x, v3.y, h[6], l[6]); bsplit2(v3.z, v3.w, h[7], l[7]);
    size_t o = (size_t)row * KP + g * 8;
    *(uint4*)&g_xh[o]     = make_uint4(h[0], h[1], h[2], h[3]);
    *(uint4*)&g_xh[o + 4] = make_uint4(h[4], h[5], h[6], h[7]);
    *(uint4*)&g_xl[o]     = make_uint4(l[0], l[1], l[2], l[3]);
    *(uint4*)&g_xl[o + 4] = make_uint4(l[4], l[5], l[6], l[7]);
}

// ---------------------------------------------------------------------------
// Prep: split weights -> [kpair][NC] packed. Device-side symbol binding.
// ---------------------------------------------------------------------------
template<int WHICH>
__global__ __launch_bounds__(256) void split_w(const float* __restrict__ W) {
    const int NC = (WHICH == 0) ? NC3 : C_;
    unsigned* outH = (WHICH == 0) ? g_wqh : g_wph;
    unsigned* outL = (WHICH == 0) ? g_wql : g_wpl;
    int idx = blockIdx.x * 256 + threadIdx.x;     // [0, KP*NC/4)
    int nc4 = NC / 4;
    int kp = idx / nc4, c4 = (idx - kp * nc4) * 4;
    float4 w0 = *(const float4*)(W + (size_t)(2 * kp) * NC + c4);
    float4 w1 = *(const float4*)(W + (size_t)(2 * kp + 1) * NC + c4);
    unsigned h[4], l[4];
    bsplit2(w0.x, w1.x, h[0], l[0]);
    bsplit2(w0.y, w1.y, h[1], l[1]);
    bsplit2(w0.z, w1.z, h[2], l[2]);
    bsplit2(w0.w, w1.w, h[3], l[3]);
    size_t o = (size_t)kp * NC + c4;
    *(uint4*)&outH[o] = make_uint4(h[0], h[1], h[2], h[3]);
    *(uint4*)&outL[o] = make_uint4(l[0], l[1], l[2], l[3]);
}

// ---------------------------------------------------------------------------
// Tensor-core GEMM, 3-term bf16, cp.async double-buffered smem pipeline.
// __launch_bounds__(256,2): cap regs at 128 so 2 CTAs stay resident
// (regfile 64K; round-11's 130 regs silently halved occupancy).
// ---------------------------------------------------------------------------
template<int MODE>
__global__ __launch_bounds__(256, 2) void tc_gemm(const float* __restrict__ bias,
                                                  float* __restrict__ outp) {
    const int NC = (MODE == 0) ? NC3 : C_;
    const unsigned* __restrict__ Axh = (MODE == 0) ? g_xh : g_oh;
    const unsigned* __restrict__ Axl = (MODE == 0) ? g_xl : g_ol;
    const unsigned* __restrict__ Wh  = (MODE == 0) ? g_wqh : g_wph;
    const unsigned* __restrict__ Wl  = (MODE == 0) ? g_wql : g_wpl;

    extern __shared__ unsigned dynsm[];
    unsigned* Ah_s = dynsm;              // [2][2560]
    unsigned* Al_s = dynsm + 5120;
    unsigned* Bh_s = dynsm + 10240;      // [2][2176]
    unsigned* Bl_s = dynsm + 14592;

    const int tid = threadIdx.x;
    const int lane = tid & 31, warp = tid >> 5;
    const int wm = (warp >> 2) * 64, wn = (warp & 3) * 32;
    const int row0 = blockIdx.y * 128, col0 = blockIdx.x * 128;
    const int fr = lane >> 2, fc = lane & 3;

    float acc[4][4][4];
    #pragma unroll
    for (int i = 0; i < 4; i++)
        #pragma unroll
        for (int j = 0; j < 4; j++)
            #pragma unroll
            for (int r = 0; r < 4; r++) acc[i][j][r] = 0.0f;

    const int am = tid >> 1;          // 0..127
    const int aseg = (tid & 1) * 8;   // kp offset within 16
    const size_t aOff = (size_t)(row0 + am) * KP + aseg;
    const int aSm = am * 20 + aseg;
    const int bSm0 = warp * 136 + lane * 4;
    const int bSm1 = (warp + 8) * 136 + lane * 4;

    auto stage = [&](int s, int k0p) {
        unsigned* AhD = Ah_s + s * 2560;
        unsigned* AlD = Al_s + s * 2560;
        unsigned* BhD = Bh_s + s * 2176;
        unsigned* BlD = Bl_s + s * 2176;
        cp_async16(&AhD[aSm],     Axh + aOff + k0p);
        cp_async16(&AhD[aSm + 4], Axh + aOff + k0p + 4);
        cp_async16(&AlD[aSm],     Axl + aOff + k0p);
        cp_async16(&AlD[aSm + 4], Axl + aOff + k0p + 4);
        const size_t b0 = (size_t)(k0p + warp) * NC + col0 + lane * 4;
        const size_t b1 = (size_t)(k0p + 8 + warp) * NC + col0 + lane * 4;
        cp_async16(&BhD[bSm0], Wh + b0);
        cp_async16(&BhD[bSm1], Wh + b1);
        cp_async16(&BlD[bSm0], Wl + b0);
        cp_async16(&BlD[bSm1], Wl + b1);
    };

    stage(0, 0); CP_COMMIT(); CP_WAIT0(); __syncthreads();

    int s = 0;
    for (int k0p = 0; k0p < KP; k0p += 16) {
        if (k0p + 16 < KP) { stage(s ^ 1, k0p + 16); CP_COMMIT(); }

        const unsigned* AhC = Ah_s + s * 2560;
        const unsigned* AlC = Al_s + s * 2560;
        const unsigned* BhC = Bh_s + s * 2176;
        const unsigned* BlC = Bl_s + s * 2176;

        #pragma unroll
        for (int kk = 0; kk < 2; kk++) {
            const int kk8 = kk * 8;
            unsigned ah[4][4], al[4][4], bh[4][2], bl[4][2];
            #pragma unroll
            for (int mt = 0; mt < 4; mt++) {
                int r0i = (wm + mt * 16 + fr) * 20;
                int r1i = r0i + 160;
                ah[mt][0] = AhC[r0i + kk8 + fc];
                ah[mt][1] = AhC[r1i + kk8 + fc];
                ah[mt][2] = AhC[r0i + kk8 + fc + 4];
                ah[mt][3] = AhC[r1i + kk8 + fc + 4];
                al[mt][0] = AlC[r0i + kk8 + fc];
                al[mt][1] = AlC[r1i + kk8 + fc];
                al[mt][2] = AlC[r0i + kk8 + fc + 4];
                al[mt][3] = AlC[r1i + kk8 + fc + 4];
            }
            #pragma unroll
            for (int nt = 0; nt < 4; nt++) {
                int c = wn + nt * 8 + fr;
                bh[nt][0] = BhC[(kk8 + fc) * 136 + c];
                bh[nt][1] = BhC[(kk8 + fc + 4) * 136 + c];
                bl[nt][0] = BlC[(kk8 + fc) * 136 + c];
                bl[nt][1] = BlC[(kk8 + fc + 4) * 136 + c];
            }
            #pragma unroll
            for (int mt = 0; mt < 4; mt++)
                #pragma unroll
                for (int nt = 0; nt < 4; nt++) {
                    mma_bf16(acc[mt][nt], ah[mt], bh[nt]);
                    mma_bf16(acc[mt][nt], al[mt], bh[nt]);
                    mma_bf16(acc[mt][nt], ah[mt], bl[nt]);
                }
        }
        CP_WAIT0();
        __syncthreads();
        s ^= 1;
    }

    // ---- epilogue ----
    #pragma unroll
    for (int mt = 0; mt < 4; mt++)
        #pragma unroll
        for (int nt = 0; nt < 4; nt++) {
            #pragma unroll
            for (int half = 0; half < 2; half++) {
                int gr = row0 + wm + mt * 16 + fr + half * 8;
                int gc = col0 + wn + nt * 8 + 2 * fc;
                float v0 = acc[mt][nt][half * 2 + 0] + bias[gc];
                float v1 = acc[mt][nt][half * 2 + 1] + bias[gc + 1];
                if (MODE == 0) {
                    int b = gr >> 10, n = gr & 1023;
                    int sq = gc / 768;
                    int rem = gc - sq * 768;
                    int h = rem >> 6, d = rem & 63;
                    float* dst = (sq == 0) ? g_q : ((sq == 1) ? g_k : g_v);
                    *(float2*)(dst + ((size_t)(b * H_ + h) * N_ + n) * HD_ + d) =
                        make_float2(v0, v1);
                } else {
                    *(float2*)(outp + (size_t)gr * NC + gc) = make_float2(v0, v1);
                }
            }
        }
}

// ---------------------------------------------------------------------------
// pack_k: RoPE + split + pack K rows -> [bh*N+key][32 dpairs] hi/lo.
// ---------------------------------------------------------------------------
__global__ __launch_bounds__(128) void pack_k(const int* __restrict__ pos_h,
                                              const int* __restrict__ pos_w) {
    int r = blockIdx.x * 128 + threadIdx.x;   // [0, BHROWS)
    int b = r / (H_ * N_);
    int n = r & (N_ - 1);
    const float* src = g_k + (size_t)r * HD_;
    int ph = pos_h[b * N_ + n], pw = pos_w[b * N_ + n];

    #pragma unroll
    for (int half = 0; half < 2; half++) {
        float t[32];
        const float4* sp = (const float4*)(src + half * 32);
        #pragma unroll
        for (int i = 0; i < 8; i++) {
            float4 v = sp[i];
            t[4*i] = v.x; t[4*i+1] = v.y; t[4*i+2] = v.z; t[4*i+3] = v.w;
        }
        float pos = (float)(half ? pw : ph);
        unsigned hh[16], ll[16];
        #pragma unroll
        for (int i = 0; i < 16; i++) {
            float sn, cs;
            sincosf(pos * exp2f(-0.83048202f * (float)i), &sn, &cs);
            int da = 2 * i, db = 2 * i + 1;
            float ra = (da & 16) ? t[da ^ 16] : -t[da ^ 16];
            float rb = (db & 16) ? t[db ^ 16] : -t[db ^ 16];
            float oa = t[da] * cs + ra * sn;
            float ob = t[db] * cs + rb * sn;
            bsplit2(oa, ob, hh[i], ll[i]);
        }
        size_t o = (size_t)r * 32 + half * 16;
        #pragma unroll
        for (int u = 0; u < 4; u++) {
            *(uint4*)&g_kph[o + 4*u] = make_uint4(hh[4*u], hh[4*u+1], hh[4*u+2], hh[4*u+3]);
            *(uint4*)&g_kpl[o + 4*u] = make_uint4(ll[4*u], ll[4*u+1], ll[4*u+2], ll[4*u+3]);
        }
    }
}

// ---------------------------------------------------------------------------
// pack_v: transpose-pack V -> [bh*64+d][512 keypairs] hi/lo.
// ---------------------------------------------------------------------------
__global__ __launch_bounds__(128) void pack_v() {
    __shared__ float sv[128][65];
    const int tid = threadIdx.x;
    const int bh = blockIdx.y, blk = blockIdx.x;   // blk: 0..7
    const float* src = g_v + ((size_t)bh * N_ + blk * 128) * HD_;

    #pragma unroll
    for (int i = 0; i < 16; i++) {
        int e = i * 128 + tid;           // float4 index
        int row = e >> 4, c4 = (e & 15) * 4;
        float4 v = *(const float4*)(src + row * HD_ + c4);
        sv[row][c4+0] = v.x; sv[row][c4+1] = v.y;
        sv[row][c4+2] = v.z; sv[row][c4+3] = v.w;
    }
    __syncthreads();

    int d = tid >> 1, half = (tid & 1) * 32;
    unsigned hh[32], ll[32];
    #pragma unroll
    for (int j = 0; j < 32; j++) {
        int kp = half + j;
        bsplit2(sv[2*kp][d], sv[2*kp+1][d], hh[j], ll[j]);
    }
    size_t o = ((size_t)bh * 64 + d) * 512 + blk * 64 + half;
    #pragma unroll
    for (int u = 0; u < 8; u++) {
        *(uint4*)&g_vph[o + 4*u] = make_uint4(hh[4*u], hh[4*u+1], hh[4*u+2], hh[4*u+3]);
        *(uint4*)&g_vpl[o + 4*u] = make_uint4(ll[4*u], ll[4*u+1], ll[4*u+2], ll[4*u+3]);
    }
}

// ---------------------------------------------------------------------------
// bf16 tensor-core flash attention, cp.async double-buffered K/V pipeline,
// Q-RoPE fused into the fragment load. __launch_bounds__(128,2).
// ---------------------------------------------------------------------------
__global__ __launch_bounds__(128, 2) void attn_tc(const int* __restrict__ pos_h,
                                                  const int* __restrict__ pos_w) {
    extern __shared__ unsigned dynsm[];
    unsigned* Kh = dynsm;               // [2][2304]
    unsigned* Kl = dynsm + 4608;
    unsigned* Vh = dynsm + 9216;
    unsigned* Vl = dynsm + 13824;

    const int b = blockIdx.z, h = blockIdx.y;
    const int tid = threadIdx.x;
    const int warp = tid >> 5, lane = tid & 31;
    const int fr = lane >> 2, fc = lane & 3;
    const int bhI = b * H_ + h;
    const size_t bh = (size_t)bhI * N_;
    const int q0 = blockIdx.x * 64 + warp * 16;
    const float SCALE = 0.125f;

    // ---- Q load + fused RoPE + split ----
    unsigned qh[4][4], ql[4][4];
    {
        const float* Qg = g_q + (bh + q0) * HD_;
        float qv[4][4][2];
        #pragma unroll
        for (int kk = 0; kk < 4; kk++)
            #pragma unroll
            for (int j = 0; j < 4; j++) {
                int r = fr + (j & 1) * 8;
                int c = kk * 16 + (j >> 1) * 8 + 2 * fc;
                qv[kk][j][0] = Qg[r * HD_ + c];
                qv[kk][j][1] = Qg[r * HD_ + c + 1];
            }
        int ph0 = pos_h[b * N_ + q0 + fr], ph1 = pos_h[b * N_ + q0 + fr + 8];
        int pw0 = pos_w[b * N_ + q0 + fr], pw1 = pos_w[b * N_ + q0 + fr + 8];
        #pragma unroll
        for (int kk = 0; kk < 4; kk++)
            #pragma unroll
            for (int j = 0; j < 4; j++) {
                int c = kk * 16 + (j >> 1) * 8 + 2 * fc;
                int i = (c & 31) >> 1;
                float pos = (float)((kk >= 2) ? ((j & 1) ? pw1 : pw0)
                                              : ((j & 1) ? ph1 : ph0));
                float sn, cs;
                sincosf(pos * exp2f(-0.83048202f * (float)i), &sn, &cs);
                float p0 = qv[kk][j][0], p1 = qv[kk][j][1];
                float o0 = qv[kk ^ 1][j][0], o1 = qv[kk ^ 1][j][1];
                float r0 = (kk & 1) ? o0 : -o0;
                float r1 = (kk & 1) ? o1 : -o1;
                bsplit2(p0 * cs + r0 * sn, p1 * cs + r1 * sn, qh[kk][j], ql[kk][j]);
            }
    }

    float o[8][4];
    #pragma unroll
    for (int nt = 0; nt < 8; nt++)
        #pragma unroll
        for (int j = 0; j < 4; j++) o[nt][j] = 0.0f;
    float m0 = -1e30f, m1 = -1e30f, l0 = 0.0f, l1 = 0.0f;

    const int key = tid >> 1, ho = (tid & 1) * 16;
    const int sofsK = key * 36 + ho;
    auto stage = [&](int s, int kt) {
        size_t gK = (bh + kt * 64 + key) * 32 + ho;
        size_t gV = ((size_t)bhI * 64 + key) * 512 + kt * 32 + ho;   // key doubles as d
        unsigned* KhD = Kh + s * 2304; unsigned* KlD = Kl + s * 2304;
        unsigned* VhD = Vh + s * 2304; unsigned* VlD = Vl + s * 2304;
        #pragma unroll
        for (int u = 0; u < 4; u++) {
            cp_async16(&KhD[sofsK + 4*u], &g_kph[gK + 4*u]);
            cp_async16(&KlD[sofsK + 4*u], &g_kpl[gK + 4*u]);
            cp_async16(&VhD[sofsK + 4*u], &g_vph[gV + 4*u]);
            cp_async16(&VlD[sofsK + 4*u], &g_vpl[gV + 4*u]);
        }
    };

    stage(0, 0); CP_COMMIT(); CP_WAIT0(); __syncthreads();

    int s = 0;
    for (int kt = 0; kt < 16; kt++) {
        if (kt + 1 < 16) { stage(s ^ 1, kt + 1); CP_COMMIT(); }

        const unsigned* KhC = Kh + s * 2304;
        const unsigned* KlC = Kl + s * 2304;
        const unsigned* VhC = Vh + s * 2304;
        const unsigned* VlC = Vl + s * 2304;

        float p[8][4];
        #pragma unroll
        for (int nt = 0; nt < 8; nt++)
            #pragma unroll
            for (int j = 0; j < 4; j++) p[nt][j] = 0.0f;

        #pragma unroll
        for (int kk = 0; kk < 4; kk++) {
            #pragma unroll
            for (int nt = 0; nt < 8; nt++) {
                int ky = nt * 8 + fr;
                int i0 = ky * 36 + kk * 8 + fc;
                unsigned kb[2]  = { KhC[i0], KhC[i0 + 4] };
                unsigned klo[2] = { KlC[i0], KlC[i0 + 4] };
                mma_bf16(p[nt], qh[kk], kb);
                mma_bf16(p[nt], ql[kk], kb);
                mma_bf16(p[nt], qh[kk], klo);
            }
        }

        float mx0 = -1e30f, mx1 = -1e30f;
        #pragma unroll
        for (int nt = 0; nt < 8; nt++) {
            mx0 = fmaxf(mx0, fmaxf(p[nt][0], p[nt][1]));
            mx1 = fmaxf(mx1, fmaxf(p[nt][2], p[nt][3]));
        }
        mx0 *= SCALE; mx1 *= SCALE;
        mx0 = fmaxf(mx0, __shfl_xor_sync(0xffffffffu, mx0, 1));
        mx0 = fmaxf(mx0, __shfl_xor_sync(0xffffffffu, mx0, 2));
        mx1 = fmaxf(mx1, __shfl_xor_sync(0xffffffffu, mx1, 1));
        mx1 = fmaxf(mx1, __shfl_xor_sync(0xffffffffu, mx1, 2));
        float mn0 = fmaxf(m0, mx0), mn1 = fmaxf(m1, mx1);
        float c0 = __expf(m0 - mn0), c1 = __expf(m1 - mn1);
        m0 = mn0; m1 = mn1;
        l0 *= c0; l1 *= c1;
        #pragma unroll
        for (int nt = 0; nt < 8; nt++) {
            o[nt][0] *= c0; o[nt][1] *= c0;
            o[nt][2] *= c1; o[nt][3] *= c1;
        }
        #pragma unroll
        for (int nt = 0; nt < 8; nt++) {
            p[nt][0] = __expf(fmaf(p[nt][0], SCALE, -mn0)); l0 += p[nt][0];
            p[nt][1] = __expf(fmaf(p[nt][1], SCALE, -mn0)); l0 += p[nt][1];
            p[nt][2] = __expf(fmaf(p[nt][2], SCALE, -mn1)); l1 += p[nt][2];
            p[nt][3] = __expf(fmaf(p[nt][3], SCALE, -mn1)); l1 += p[nt][3];
        }

        #pragma unroll
        for (int kk2 = 0; kk2 < 4; kk2++) {
            unsigned pah[4], pal[4];
            bsplit2(p[2*kk2][0],   p[2*kk2][1],   pah[0], pal[0]);
            bsplit2(p[2*kk2][2],   p[2*kk2][3],   pah[1], pal[1]);
            bsplit2(p[2*kk2+1][0], p[2*kk2+1][1], pah[2], pal[2]);
            bsplit2(p[2*kk2+1][2], p[2*kk2+1][3], pah[3], pal[3]);
            #pragma unroll
            for (int nt = 0; nt < 8; nt++) {
                int d = nt * 8 + fr;
                int i0 = d * 36 + kk2 * 8 + fc;
                unsigned vb[2]  = { VhC[i0], VhC[i0 + 4] };
                unsigned vlo[2] = { VlC[i0], VlC[i0 + 4] };
                mma_bf16(o[nt], pah, vb);
                mma_bf16(o[nt], pal, vb);
                mma_bf16(o[nt], pah, vlo);
            }
        }
        CP_WAIT0();
        __syncthreads();
        s ^= 1;
    }

    // ---- finalize: write packed hi/lo o (pairs along C) ----
    l0 += __shfl_xor_sync(0xffffffffu, l0, 1);
    l0 += __shfl_xor_sync(0xffffffffu, l0, 2);
    l1 += __shfl_xor_sync(0xffffffffu, l1, 1);
    l1 += __shfl_xor_sync(0xffffffffu, l1, 2);
    float il0 = 1.0f / l0, il1 = 1.0f / l1;

    size_t row0 = (size_t)(b * N_ + q0 + fr) * KP;
    size_t row1 = row0 + 8 * KP;
    #pragma unroll
    for (int nt = 0; nt < 8; nt++) {
        int kp = h * 32 + nt * 4 + fc;
        unsigned hh, ll;
        bsplit2(o[nt][0] * il0, o[nt][1] * il0, hh, ll);
        g_oh[row0 + kp] = hh; g_ol[row0 + kp] = ll;
        bsplit2(o[nt][2] * il1, o[nt][3] * il1, hh, ll);
        g_oh[row1 + kp] = hh; g_ol[row1 + kp] = ll;
    }
}

extern "C" void kernel_launch(void* const* d_in, const int* in_sizes, int n_in,
                              void* d_out, int out_size) {
    const float* x      = (const float*)d_in[0];
    const float* W_qkv  = (const float*)d_in[1];
    const float* b_qkv  = (const float*)d_in[2];
    const float* W_proj = (const float*)d_in[3];
    const float* b_proj = (const float*)d_in[4];
    const int*   pos_h  = (const int*)d_in[5];
    const int*   pos_w  = (const int*)d_in[6];
    float* out = (float*)d_out;

    const int GEMM_SMEM = 75776;
    const int ATTN_SMEM = 73728;
    cudaFuncSetAttribute(tc_gemm<0>, cudaFuncAttributeMaxDynamicSharedMemorySize, GEMM_SMEM);
    cudaFuncSetAttribute(tc_gemm<1>, cudaFuncAttributeMaxDynamicSharedMemorySize, GEMM_SMEM);
    cudaFuncSetAttribute(attn_tc,    cudaFuncAttributeMaxDynamicSharedMemorySize, ATTN_SMEM);

    split_x<<<(MROWS * 48) / 256, 256>>>(x);
    split_w<0><<<(KP * (NC3 / 4)) / 256, 256>>>(W_qkv);
    split_w<1><<<(KP * (C_ / 4)) / 256, 256>>>(W_proj);

    tc_gemm<0><<<dim3(NC3 / 128, MROWS / 128), 256, GEMM_SMEM>>>(b_qkv, nullptr);

    pack_k<<<BHROWS / 128, 128>>>(pos_h, pos_w);
    pack_v<<<dim3(8, B_ * H_), 128>>>();

    attn_tc<<<dim3(N_ / 64, H_, B_), 128, ATTN_SMEM>>>(pos_h, pos_w);

    tc_gemm<1><<<dim3(C_ / 128, MROWS / 128), 256, GEMM_SMEM>>>(b_proj, out);
}

// round 13
// speedup vs baseline: 1.4007x; 1.4007x over previous
#include <cuda_runtime.h>
#include <cuda_bf16.h>
#include <math.h>

#define B_  16
#define N_  1024
#define C_  768
#define H_  12
#define HD_ 64
#define NC3 2304
#define MROWS (B_*N_)
#define KP  (C_/2)          // 384 k-pairs
#define BHROWS (B_*H_*N_)   // 196608

// f32 scratch
__device__ float g_q[B_*H_*N_*HD_];
__device__ float g_k[B_*H_*N_*HD_];
__device__ float g_v[B_*H_*N_*HD_];
// packed bf16x2 (pairs along k) scratch
__device__ unsigned g_xh[MROWS*KP],  g_xl[MROWS*KP];
__device__ unsigned g_wqh[KP*NC3],   g_wql[KP*NC3];
__device__ unsigned g_wph[KP*C_],    g_wpl[KP*C_];
__device__ unsigned g_oh[MROWS*KP],  g_ol[MROWS*KP];
__device__ unsigned g_kph[BHROWS*32], g_kpl[BHROWS*32];       // [bh*N+key][dpair]
__device__ unsigned g_vph[B_*H_*64*512], g_vpl[B_*H_*64*512]; // [bh*64+d][keypair]

// ---------------------------------------------------------------------------
// helpers
// ---------------------------------------------------------------------------
__device__ __forceinline__ void bsplit2(float x, float y, unsigned& h, unsigned& l) {
    unsigned hb;
    asm("cvt.rn.bf16x2.f32 %0, %1, %2;" : "=r"(hb) : "f"(y), "f"(x));
    float hx = __uint_as_float(hb << 16);
    float hy = __uint_as_float(hb & 0xffff0000u);
    unsigned lb;
    asm("cvt.rn.bf16x2.f32 %0, %1, %2;" : "=r"(lb) : "f"(y - hy), "f"(x - hx));
    h = hb; l = lb;
}

__device__ __forceinline__ void mma_bf16(float d[4], const unsigned a[4], const unsigned b[2]) {
    asm volatile(
        "mma.sync.aligned.m16n8k16.row.col.f32.bf16.bf16.f32 "
        "{%0,%1,%2,%3}, {%4,%5,%6,%7}, {%8,%9}, {%0,%1,%2,%3};"
        : "+f"(d[0]), "+f"(d[1]), "+f"(d[2]), "+f"(d[3])
        : "r"(a[0]), "r"(a[1]), "r"(a[2]), "r"(a[3]), "r"(b[0]), "r"(b[1]));
}

__device__ __forceinline__ void cp_async16(void* sptr, const void* gptr) {
    unsigned s = (unsigned)__cvta_generic_to_shared(sptr);
    asm volatile("cp.async.cg.shared.global [%0], [%1], 16;" :: "r"(s), "l"(gptr));
}
#define CP_COMMIT() asm volatile("cp.async.commit_group;" ::: "memory")
#define CP_WAIT0()  asm volatile("cp.async.wait_group 0;" ::: "memory")

// ---------------------------------------------------------------------------
// Prep: split x into packed hi/lo (pairs along k).
// ---------------------------------------------------------------------------
__global__ __launch_bounds__(256) void split_x(const float* __restrict__ X) {
    int idx = blockIdx.x * 256 + threadIdx.x;     // [0, MROWS*48)
    int row = idx / 48, g = idx - row * 48;
    const float4* p = (const float4*)(X + (size_t)row * C_ + g * 16);
    float4 v0 = p[0], v1 = p[1], v2 = p[2], v3 = p[3];
    unsigned h[8], l[8];
    bsplit2(v0.x, v0.y, h[0], l[0]); bsplit2(v0.z, v0.w, h[1], l[1]);
    bsplit2(v1.x, v1.y, h[2], l[2]); bsplit2(v1.z, v1.w, h[3], l[3]);
    bsplit2(v2.x, v2.y, h[4], l[4]); bsplit2(v2.z, v2.w, h[5], l[5]);
    bsplit2(v3.x, v3.y, h[6], l[6]); bsplit2(v3.z, v3.w, h[7], l[7]);
    size_t o = (size_t)row * KP + g * 8;
    *(uint4*)&g_xh[o]     = make_uint4(h[0], h[1], h[2], h[3]);
    *(uint4*)&g_xh[o + 4] = make_uint4(h[4], h[5], h[6], h[7]);
    *(uint4*)&g_xl[o]     = make_uint4(l[0], l[1], l[2], l[3]);
    *(uint4*)&g_xl[o + 4] = make_uint4(l[4], l[5], l[6], l[7]);
}

// ---------------------------------------------------------------------------
// Prep: split weights -> [kpair][NC] packed. Device-side symbol binding.
// ---------------------------------------------------------------------------
template<int WHICH>
__global__ __launch_bounds__(256) void split_w(const float* __restrict__ W) {
    const int NC = (WHICH == 0) ? NC3 : C_;
    unsigned* outH = (WHICH == 0) ? g_wqh : g_wph;
    unsigned* outL = (WHICH == 0) ? g_wql : g_wpl;
    int idx = blockIdx.x * 256 + threadIdx.x;     // [0, KP*NC/4)
    int nc4 = NC / 4;
    int kp = idx / nc4, c4 = (idx - kp * nc4) * 4;
    float4 w0 = *(const float4*)(W + (size_t)(2 * kp) * NC + c4);
    float4 w1 = *(const float4*)(W + (size_t)(2 * kp + 1) * NC + c4);
    unsigned h[4], l[4];
    bsplit2(w0.x, w1.x, h[0], l[0]);
    bsplit2(w0.y, w1.y, h[1], l[1]);
    bsplit2(w0.z, w1.z, h[2], l[2]);
    bsplit2(w0.w, w1.w, h[3], l[3]);
    size_t o = (size_t)kp * NC + c4;
    *(uint4*)&outH[o] = make_uint4(h[0], h[1], h[2], h[3]);
    *(uint4*)&outL[o] = make_uint4(l[0], l[1], l[2], l[3]);
}

// ---------------------------------------------------------------------------
// Tensor-core GEMM on pre-split packed operands, 3-term bf16.
// Round-10 measured-best variant: static smem, LDG->reg->STS staging,
// natural 128 regs / 2 CTAs per SM. (cp.async + occupancy hints both
// regressed this kernel — rounds 11/12.)
// ---------------------------------------------------------------------------
template<int MODE>
__global__ __launch_bounds__(256) void tc_gemm(const float* __restrict__ bias,
                                               float* __restrict__ outp) {
    const int NC = (MODE == 0) ? NC3 : C_;
    const unsigned* __restrict__ Axh = (MODE == 0) ? g_xh : g_oh;
    const unsigned* __restrict__ Axl = (MODE == 0) ? g_xl : g_ol;
    const unsigned* __restrict__ Wh  = (MODE == 0) ? g_wqh : g_wph;
    const unsigned* __restrict__ Wl  = (MODE == 0) ? g_wql : g_wpl;

    __shared__ unsigned Ah_s[128 * 20], Al_s[128 * 20];
    __shared__ unsigned Bh_s[16 * 136], Bl_s[16 * 136];

    const int tid = threadIdx.x;
    const int lane = tid & 31, warp = tid >> 5;
    const int wm = (warp >> 2) * 64, wn = (warp & 3) * 32;
    const int row0 = blockIdx.y * 128, col0 = blockIdx.x * 128;
    const int fr = lane >> 2, fc = lane & 3;

    float acc[4][4][4];
    #pragma unroll
    for (int i = 0; i < 4; i++)
        #pragma unroll
        for (int j = 0; j < 4; j++)
            #pragma unroll
            for (int r = 0; r < 4; r++) acc[i][j][r] = 0.0f;

    const int am = tid >> 1;          // 0..127
    const int aseg = (tid & 1) * 8;   // kp offset within 16

    for (int k0p = 0; k0p < KP; k0p += 16) {
        const uint4* pa_h = (const uint4*)(Axh + (size_t)(row0 + am) * KP + k0p + aseg);
        const uint4* pa_l = (const uint4*)(Axl + (size_t)(row0 + am) * KP + k0p + aseg);
        uint4 a_h0 = pa_h[0], a_h1 = pa_h[1];
        uint4 a_l0 = pa_l[0], a_l1 = pa_l[1];
        uint4 b_h0 = *(const uint4*)(Wh + (size_t)(k0p + warp) * NC + col0 + lane * 4);
        uint4 b_h1 = *(const uint4*)(Wh + (size_t)(k0p + 8 + warp) * NC + col0 + lane * 4);
        uint4 b_l0 = *(const uint4*)(Wl + (size_t)(k0p + warp) * NC + col0 + lane * 4);
        uint4 b_l1 = *(const uint4*)(Wl + (size_t)(k0p + 8 + warp) * NC + col0 + lane * 4);

        __syncthreads();   // previous iter's fragment reads done

        *(uint4*)&Ah_s[am * 20 + aseg]     = a_h0;
        *(uint4*)&Ah_s[am * 20 + aseg + 4] = a_h1;
        *(uint4*)&Al_s[am * 20 + aseg]     = a_l0;
        *(uint4*)&Al_s[am * 20 + aseg + 4] = a_l1;
        *(uint4*)&Bh_s[warp * 136 + lane * 4]       = b_h0;
        *(uint4*)&Bh_s[(warp + 8) * 136 + lane * 4] = b_h1;
        *(uint4*)&Bl_s[warp * 136 + lane * 4]       = b_l0;
        *(uint4*)&Bl_s[(warp + 8) * 136 + lane * 4] = b_l1;
        __syncthreads();

        #pragma unroll
        for (int kk = 0; kk < 2; kk++) {
            const int kk8 = kk * 8;
            unsigned ah[4][4], al[4][4], bh[4][2], bl[4][2];
            #pragma unroll
            for (int mt = 0; mt < 4; mt++) {
                int r0i = (wm + mt * 16 + fr) * 20;
                int r1i = r0i + 160;
                ah[mt][0] = Ah_s[r0i + kk8 + fc];
                ah[mt][1] = Ah_s[r1i + kk8 + fc];
                ah[mt][2] = Ah_s[r0i + kk8 + fc + 4];
                ah[mt][3] = Ah_s[r1i + kk8 + fc + 4];
                al[mt][0] = Al_s[r0i + kk8 + fc];
                al[mt][1] = Al_s[r1i + kk8 + fc];
                al[mt][2] = Al_s[r0i + kk8 + fc + 4];
                al[mt][3] = Al_s[r1i + kk8 + fc + 4];
            }
            #pragma unroll
            for (int nt = 0; nt < 4; nt++) {
                int c = wn + nt * 8 + fr;
                bh[nt][0] = Bh_s[(kk8 + fc) * 136 + c];
                bh[nt][1] = Bh_s[(kk8 + fc + 4) * 136 + c];
                bl[nt][0] = Bl_s[(kk8 + fc) * 136 + c];
                bl[nt][1] = Bl_s[(kk8 + fc + 4) * 136 + c];
            }
            #pragma unroll
            for (int mt = 0; mt < 4; mt++)
                #pragma unroll
                for (int nt = 0; nt < 4; nt++) {
                    mma_bf16(acc[mt][nt], ah[mt], bh[nt]);
                    mma_bf16(acc[mt][nt], al[mt], bh[nt]);
                    mma_bf16(acc[mt][nt], ah[mt], bl[nt]);
                }
        }
    }

    // ---- epilogue ----
    #pragma unroll
    for (int mt = 0; mt < 4; mt++)
        #pragma unroll
        for (int nt = 0; nt < 4; nt++) {
            #pragma unroll
            for (int half = 0; half < 2; half++) {
                int gr = row0 + wm + mt * 16 + fr + half * 8;
                int gc = col0 + wn + nt * 8 + 2 * fc;
                float v0 = acc[mt][nt][half * 2 + 0] + bias[gc];
                float v1 = acc[mt][nt][half * 2 + 1] + bias[gc + 1];
                if (MODE == 0) {
                    int b = gr >> 10, n = gr & 1023;
                    int sq = gc / 768;
                    int rem = gc - sq * 768;
                    int h = rem >> 6, d = rem & 63;
                    float* dst = (sq == 0) ? g_q : ((sq == 1) ? g_k : g_v);
                    *(float2*)(dst + ((size_t)(b * H_ + h) * N_ + n) * HD_ + d) =
                        make_float2(v0, v1);
                } else {
                    *(float2*)(outp + (size_t)gr * NC + gc) = make_float2(v0, v1);
                }
            }
        }
}

// ---------------------------------------------------------------------------
// pack_k: RoPE + split + pack K rows -> [bh*N+key][32 dpairs] hi/lo.
// ---------------------------------------------------------------------------
__global__ __launch_bounds__(128) void pack_k(const int* __restrict__ pos_h,
                                              const int* __restrict__ pos_w) {
    int r = blockIdx.x * 128 + threadIdx.x;   // [0, BHROWS)
    int b = r / (H_ * N_);
    int n = r & (N_ - 1);
    const float* src = g_k + (size_t)r * HD_;
    int ph = pos_h[b * N_ + n], pw = pos_w[b * N_ + n];

    #pragma unroll
    for (int half = 0; half < 2; half++) {
        float t[32];
        const float4* sp = (const float4*)(src + half * 32);
        #pragma unroll
        for (int i = 0; i < 8; i++) {
            float4 v = sp[i];
            t[4*i] = v.x; t[4*i+1] = v.y; t[4*i+2] = v.z; t[4*i+3] = v.w;
        }
        float pos = (float)(half ? pw : ph);
        unsigned hh[16], ll[16];
        #pragma unroll
        for (int i = 0; i < 16; i++) {
            float sn, cs;
            sincosf(pos * exp2f(-0.83048202f * (float)i), &sn, &cs);
            int da = 2 * i, db = 2 * i + 1;
            float ra = (da & 16) ? t[da ^ 16] : -t[da ^ 16];
            float rb = (db & 16) ? t[db ^ 16] : -t[db ^ 16];
            float oa = t[da] * cs + ra * sn;
            float ob = t[db] * cs + rb * sn;
            bsplit2(oa, ob, hh[i], ll[i]);
        }
        size_t o = (size_t)r * 32 + half * 16;
        #pragma unroll
        for (int u = 0; u < 4; u++) {
            *(uint4*)&g_kph[o + 4*u] = make_uint4(hh[4*u], hh[4*u+1], hh[4*u+2], hh[4*u+3]);
            *(uint4*)&g_kpl[o + 4*u] = make_uint4(ll[4*u], ll[4*u+1], ll[4*u+2], ll[4*u+3]);
        }
    }
}

// ---------------------------------------------------------------------------
// pack_v: transpose-pack V -> [bh*64+d][512 keypairs] hi/lo.
// ---------------------------------------------------------------------------
__global__ __launch_bounds__(128) void pack_v() {
    __shared__ float sv[128][65];
    const int tid = threadIdx.x;
    const int bh = blockIdx.y, blk = blockIdx.x;   // blk: 0..7
    const float* src = g_v + ((size_t)bh * N_ + blk * 128) * HD_;

    #pragma unroll
    for (int i = 0; i < 16; i++) {
        int e = i * 128 + tid;           // float4 index
        int row = e >> 4, c4 = (e & 15) * 4;
        float4 v = *(const float4*)(src + row * HD_ + c4);
        sv[row][c4+0] = v.x; sv[row][c4+1] = v.y;
        sv[row][c4+2] = v.z; sv[row][c4+3] = v.w;
    }
    __syncthreads();

    int d = tid >> 1, half = (tid & 1) * 32;
    unsigned hh[32], ll[32];
    #pragma unroll
    for (int j = 0; j < 32; j++) {
        int kp = half + j;
        bsplit2(sv[2*kp][d], sv[2*kp+1][d], hh[j], ll[j]);
    }
    size_t o = ((size_t)bh * 64 + d) * 512 + blk * 64 + half;
    #pragma unroll
    for (int u = 0; u < 8; u++) {
        *(uint4*)&g_vph[o + 4*u] = make_uint4(hh[4*u], hh[4*u+1], hh[4*u+2], hh[4*u+3]);
        *(uint4*)&g_vpl[o + 4*u] = make_uint4(ll[4*u], ll[4*u+1], ll[4*u+2], ll[4*u+3]);
    }
}

// ---------------------------------------------------------------------------
// bf16 tensor-core flash attention, cp.async double-buffered K/V pipeline,
// Q-RoPE fused into the fragment load. Round-11 measured-best variant
// (no occupancy hint — 2 CTAs/SM is already natural).
// ---------------------------------------------------------------------------
__global__ __launch_bounds__(128) void attn_tc(const int* __restrict__ pos_h,
                                               const int* __restrict__ pos_w) {
    extern __shared__ unsigned dynsm[];
    unsigned* Kh = dynsm;               // [2][2304]
    unsigned* Kl = dynsm + 4608;
    unsigned* Vh = dynsm + 9216;
    unsigned* Vl = dynsm + 13824;

    const int b = blockIdx.z, h = blockIdx.y;
    const int tid = threadIdx.x;
    const int warp = tid >> 5, lane = tid & 31;
    const int fr = lane >> 2, fc = lane & 3;
    const int bhI = b * H_ + h;
    const size_t bh = (size_t)bhI * N_;
    const int q0 = blockIdx.x * 64 + warp * 16;
    const float SCALE = 0.125f;

    // ---- Q load + fused RoPE + split ----
    unsigned qh[4][4], ql[4][4];
    {
        const float* Qg = g_q + (bh + q0) * HD_;
        float qv[4][4][2];
        #pragma unroll
        for (int kk = 0; kk < 4; kk++)
            #pragma unroll
            for (int j = 0; j < 4; j++) {
                int r = fr + (j & 1) * 8;
                int c = kk * 16 + (j >> 1) * 8 + 2 * fc;
                qv[kk][j][0] = Qg[r * HD_ + c];
                qv[kk][j][1] = Qg[r * HD_ + c + 1];
            }
        int ph0 = pos_h[b * N_ + q0 + fr], ph1 = pos_h[b * N_ + q0 + fr + 8];
        int pw0 = pos_w[b * N_ + q0 + fr], pw1 = pos_w[b * N_ + q0 + fr + 8];
        #pragma unroll
        for (int kk = 0; kk < 4; kk++)
            #pragma unroll
            for (int j = 0; j < 4; j++) {
                int c = kk * 16 + (j >> 1) * 8 + 2 * fc;
                int i = (c & 31) >> 1;
                float pos = (float)((kk >= 2) ? ((j & 1) ? pw1 : pw0)
                                              : ((j & 1) ? ph1 : ph0));
                float sn, cs;
                sincosf(pos * exp2f(-0.83048202f * (float)i), &sn, &cs);
                float p0 = qv[kk][j][0], p1 = qv[kk][j][1];
                float o0 = qv[kk ^ 1][j][0], o1 = qv[kk ^ 1][j][1];
                float r0 = (kk & 1) ? o0 : -o0;
                float r1 = (kk & 1) ? o1 : -o1;
                bsplit2(p0 * cs + r0 * sn, p1 * cs + r1 * sn, qh[kk][j], ql[kk][j]);
            }
    }

    float o[8][4];
    #pragma unroll
    for (int nt = 0; nt < 8; nt++)
        #pragma unroll
        for (int j = 0; j < 4; j++) o[nt][j] = 0.0f;
    float m0 = -1e30f, m1 = -1e30f, l0 = 0.0f, l1 = 0.0f;

    const int key = tid >> 1, ho = (tid & 1) * 16;
    const int sofsK = key * 36 + ho;
    auto stage = [&](int s, int kt) {
        size_t gK = (bh + kt * 64 + key) * 32 + ho;
        size_t gV = ((size_t)bhI * 64 + key) * 512 + kt * 32 + ho;   // key doubles as d
        unsigned* KhD = Kh + s * 2304; unsigned* KlD = Kl + s * 2304;
        unsigned* VhD = Vh + s * 2304; unsigned* VlD = Vl + s * 2304;
        #pragma unroll
        for (int u = 0; u < 4; u++) {
            cp_async16(&KhD[sofsK + 4*u], &g_kph[gK + 4*u]);
            cp_async16(&KlD[sofsK + 4*u], &g_kpl[gK + 4*u]);
            cp_async16(&VhD[sofsK + 4*u], &g_vph[gV + 4*u]);
            cp_async16(&VlD[sofsK + 4*u], &g_vpl[gV + 4*u]);
        }
    };

    stage(0, 0); CP_COMMIT(); CP_WAIT0(); __syncthreads();

    int s = 0;
    for (int kt = 0; kt < 16; kt++) {
        if (kt + 1 < 16) { stage(s ^ 1, kt + 1); CP_COMMIT(); }

        const unsigned* KhC = Kh + s * 2304;
        const unsigned* KlC = Kl + s * 2304;
        const unsigned* VhC = Vh + s * 2304;
        const unsigned* VlC = Vl + s * 2304;

        float p[8][4];
        #pragma unroll
        for (int nt = 0; nt < 8; nt++)
            #pragma unroll
            for (int j = 0; j < 4; j++) p[nt][j] = 0.0f;

        #pragma unroll
        for (int kk = 0; kk < 4; kk++) {
            #pragma unroll
            for (int nt = 0; nt < 8; nt++) {
                int ky = nt * 8 + fr;
                int i0 = ky * 36 + kk * 8 + fc;
                unsigned kb[2]  = { KhC[i0], KhC[i0 + 4] };
                unsigned klo[2] = { KlC[i0], KlC[i0 + 4] };
                mma_bf16(p[nt], qh[kk], kb);
                mma_bf16(p[nt], ql[kk], kb);
                mma_bf16(p[nt], qh[kk], klo);
            }
        }

        float mx0 = -1e30f, mx1 = -1e30f;
        #pragma unroll
        for (int nt = 0; nt < 8; nt++) {
            mx0 = fmaxf(mx0, fmaxf(p[nt][0], p[nt][1]));
            mx1 = fmaxf(mx1, fmaxf(p[nt][2], p[nt][3]));
        }
        mx0 *= SCALE; mx1 *= SCALE;
        mx0 = fmaxf(mx0, __shfl_xor_sync(0xffffffffu, mx0, 1));
        mx0 = fmaxf(mx0, __shfl_xor_sync(0xffffffffu, mx0, 2));
        mx1 = fmaxf(mx1, __shfl_xor_sync(0xffffffffu, mx1, 1));
        mx1 = fmaxf(mx1, __shfl_xor_sync(0xffffffffu, mx1, 2));
        float mn0 = fmaxf(m0, mx0), mn1 = fmaxf(m1, mx1);
        float c0 = __expf(m0 - mn0), c1 = __expf(m1 - mn1);
        m0 = mn0; m1 = mn1;
        l0 *= c0; l1 *= c1;
        #pragma unroll
        for (int nt = 0; nt < 8; nt++) {
            o[nt][0] *= c0; o[nt][1] *= c0;
            o[nt][2] *= c1; o[nt][3] *= c1;
        }
        #pragma unroll
        for (int nt = 0; nt < 8; nt++) {
            p[nt][0] = __expf(fmaf(p[nt][0], SCALE, -mn0)); l0 += p[nt][0];
            p[nt][1] = __expf(fmaf(p[nt][1], SCALE, -mn0)); l0 += p[nt][1];
            p[nt][2] = __expf(fmaf(p[nt][2], SCALE, -mn1)); l1 += p[nt][2];
            p[nt][3] = __expf(fmaf(p[nt][3], SCALE, -mn1)); l1 += p[nt][3];
        }

        #pragma unroll
        for (int kk2 = 0; kk2 < 4; kk2++) {
            unsigned pah[4], pal[4];
            bsplit2(p[2*kk2][0],   p[2*kk2][1],   pah[0], pal[0]);
            bsplit2(p[2*kk2][2],   p[2*kk2][3],   pah[1], pal[1]);
            bsplit2(p[2*kk2+1][0], p[2*kk2+1][1], pah[2], pal[2]);
            bsplit2(p[2*kk2+1][2], p[2*kk2+1][3], pah[3], pal[3]);
            #pragma unroll
            for (int nt = 0; nt < 8; nt++) {
                int d = nt * 8 + fr;
                int i0 = d * 36 + kk2 * 8 + fc;
                unsigned vb[2]  = { VhC[i0], VhC[i0 + 4] };
                unsigned vlo[2] = { VlC[i0], VlC[i0 + 4] };
                mma_bf16(o[nt], pah, vb);
                mma_bf16(o[nt], pal, vb);
                mma_bf16(o[nt], pah, vlo);
            }
        }
        CP_WAIT0();
        __syncthreads();
        s ^= 1;
    }

    // ---- finalize: write packed hi/lo o (pairs along C) ----
    l0 += __shfl_xor_sync(0xffffffffu, l0, 1);
    l0 += __shfl_xor_sync(0xffffffffu, l0, 2);
    l1 += __shfl_xor_sync(0xffffffffu, l1, 1);
    l1 += __shfl_xor_sync(0xffffffffu, l1, 2);
    float il0 = 1.0f / l0, il1 = 1.0f / l1;

    size_t row0 = (size_t)(b * N_ + q0 + fr) * KP;
    size_t row1 = row0 + 8 * KP;
    #pragma unroll
    for (int nt = 0; nt < 8; nt++) {
        int kp = h * 32 + nt * 4 + fc;
        unsigned hh, ll;
        bsplit2(o[nt][0] * il0, o[nt][1] * il0, hh, ll);
        g_oh[row0 + kp] = hh; g_ol[row0 + kp] = ll;
        bsplit2(o[nt][2] * il1, o[nt][3] * il1, hh, ll);
        g_oh[row1 + kp] = hh; g_ol[row1 + kp] = ll;
    }
}

extern "C" void kernel_launch(void* const* d_in, const int* in_sizes, int n_in,
                              void* d_out, int out_size) {
    const float* x      = (const float*)d_in[0];
    const float* W_qkv  = (const float*)d_in[1];
    const float* b_qkv  = (const float*)d_in[2];
    const float* W_proj = (const float*)d_in[3];
    const float* b_proj = (const float*)d_in[4];
    const int*   pos_h  = (const int*)d_in[5];
    const int*   pos_w  = (const int*)d_in[6];
    float* out = (float*)d_out;

    const int ATTN_SMEM = 73728;
    cudaFuncSetAttribute(attn_tc, cudaFuncAttributeMaxDynamicSharedMemorySize, ATTN_SMEM);

    split_x<<<(MROWS * 48) / 256, 256>>>(x);
    split_w<0><<<(KP * (NC3 / 4)) / 256, 256>>>(W_qkv);
    split_w<1><<<(KP * (C_ / 4)) / 256, 256>>>(W_proj);

    tc_gemm<0><<<dim3(NC3 / 128, MROWS / 128), 256>>>(b_qkv, nullptr);

    pack_k<<<BHROWS / 128, 128>>>(pos_h, pos_w);
    pack_v<<<dim3(8, B_ * H_), 128>>>();

    attn_tc<<<dim3(N_ / 64, H_, B_), 128, ATTN_SMEM>>>(pos_h, pos_w);

    tc_gemm<1><<<dim3(C_ / 128, MROWS / 128), 256>>>(b_proj, out);
}